// round 13
// baseline (speedup 1.0000x reference)
#include <cuda_runtime.h>
#include <math_constants.h>

// ---------------------------------------------------------------------------
// ReverseLossLayer: loss = 0.5 * sum_m  min_n || src[n] - tar[m] ||^2
// Exact 1-NN via 2-D (x,y) bucket grid, 48x48 over [-5,5]^2. 3 graph nodes:
//   build -> query(3x3, flag insufficient) -> fixup(block/target + finish)
// State contract: g_cnt / g_acc / g_flagcnt / g_done are ZERO at entry (CUDA
// zero-init on first call; the fixup last-block re-zeros for the next replay).
// Bucket slot order is nondeterministic but min over a bucket is
// order-invariant; reduction uses exact fixed-point u64 atomics.
// ---------------------------------------------------------------------------

#define MAX_M 16384
#define G2 48
#define NC2 (G2 * G2)               // 2304 cells
#define CAP 192                     // lambda_max ~ 113; overflow P ~ 1e-11
#define BASEC (-5.0f)
#define INVH 4.8f                   // G2 / 10
#define FIXSCALE 4294967296.0       // 2^32
#define RMAX 4                      // ring cutoff; beyond -> brute force
#define FIXUP_BLOCKS 296

__device__ int                g_cnt[NC2];          // zero-init
__device__ float4             g_b[NC2 * CAP];      // ~14 MB bucket scratch
__device__ float4             g_all[MAX_M];        // compact unordered copy
__device__ float              g_min[MAX_M];
__device__ unsigned long long g_acc;               // zero-init
__device__ int                g_flag[MAX_M];
__device__ int                g_flagcnt;           // zero-init
__device__ int                g_done;              // zero-init

__device__ __forceinline__ int cell_of(float v) {
    int c = (int)floorf((v - BASEC) * INVH);
    return min(max(c, 0), G2 - 1);
}

// Sufficient xy-index radius: any point with d < sqrt(best) lies within
// index distance floor(sqrt(best)*INVH) + 1 (clamping only contracts).
__device__ __forceinline__ int rn_of(float best) {
    if (!(best < CUDART_INF_F)) return 1 << 20;
    return (int)fmaf(sqrtf(best), INVH, 1.001f);
}

__device__ __forceinline__ unsigned long long fix_of(float best) {
    return (unsigned long long)((double)best * FIXSCALE);
}

__global__ void rl_build_kernel(const float* __restrict__ src, int N) {
    const int i = blockIdx.x * blockDim.x + threadIdx.x;
    if (i >= N) return;
    const float x = src[3*i], y = src[3*i+1], z = src[3*i+2];
    g_all[i] = make_float4(x, y, z, 0.0f);          // compact copy for brute
    const int cell = cell_of(x) * G2 + cell_of(y);
    const int slot = atomicAdd(&g_cnt[cell], 1);
    if (slot < CAP) g_b[cell * CAP + slot] = make_float4(x, y, z, 0.0f);
}

// Warp per target: 3x3 xy cells; counts PREFETCHED (9 independent loads),
// then every lane strides each bucket's contiguous float4 points.
__global__ __launch_bounds__(256)
void rl_query_kernel(const float* __restrict__ tar, int M) {
    const int gtid = blockIdx.x * blockDim.x + threadIdx.x;
    const int t = gtid >> 5, lane = gtid & 31;
    if (t >= M) return;

    const float tx = tar[3*t], ty = tar[3*t+1], tz = tar[3*t+2];
    const int cx = cell_of(tx), cy = cell_of(ty);

    // Prefetch all 9 cell ids + counts (independent loads -> one L2 latency).
    int cells[9], cnts[9];
    #pragma unroll
    for (int i = 0; i < 9; i++) {
        const int x = cx + i / 3 - 1;
        const int y = cy + i % 3 - 1;
        const bool ok = (x >= 0 && x < G2 && y >= 0 && y < G2);
        const int cell = ok ? (x * G2 + y) : 0;
        cells[i] = cell;
        cnts[i] = ok ? min(g_cnt[cell], CAP) : 0;
    }

    float best = CUDART_INF_F;
    #pragma unroll
    for (int i = 0; i < 9; i++) {
        const int cnt = cnts[i];
        const float4* __restrict__ p = &g_b[cells[i] * CAP];
        for (int k = lane; k < cnt; k += 32) {
            const float4 s = p[k];
            const float ddx = s.x - tx, ddy = s.y - ty, ddz = s.z - tz;
            best = fminf(best, fmaf(ddz, ddz, fmaf(ddy, ddy, ddx * ddx)));
        }
    }
    #pragma unroll
    for (int o = 16; o > 0; o >>= 1)
        best = fminf(best, __shfl_xor_sync(0xFFFFFFFFu, best, o));

    if (lane == 0) {
        g_min[t] = best;
        if (rn_of(best) <= 1) atomicAdd(&g_acc, fix_of(best));
        else                  g_flag[atomicAdd(&g_flagcnt, 1)] = t;
    }
}

// BLOCK per flagged target; last finished block writes the output and resets
// all mutated persistent state (graph-replay determinism).
__global__ __launch_bounds__(256)
void rl_fixup_kernel(const float* __restrict__ tar, int N,
                     float* __restrict__ out) {
    __shared__ float shf[256];
    __shared__ int sh_last;
    const int tid = threadIdx.x;
    const int nf = g_flagcnt;

    for (int fi = blockIdx.x; fi < nf; fi += gridDim.x) {
        const int t = g_flag[fi];
        const float tx = tar[3*t], ty = tar[3*t+1], tz = tar[3*t+2];

        const float seed = g_min[t];
        const int Rn = rn_of(seed);
        float b = CUDART_INF_F;

        if (Rn <= RMAX) {
            // (2Rn+1)^2 cells minus inner 3x3; cell group = tid/8 (32 groups),
            // sub-lane = tid%8 strides the bucket -> coalesced 128B reads.
            const int cx = cell_of(tx), cy = cell_of(ty);
            const int grp = tid >> 3, sub = tid & 7;
            const int W2 = 2 * Rn + 1, ncells = W2 * W2;
            for (int c = grp; c < ncells; c += 32) {
                const int ddx = c / W2 - Rn;
                const int ddy = c % W2 - Rn;
                if (abs(ddx) <= 1 && abs(ddy) <= 1) continue;   // 3x3 done
                const int x = cx + ddx, y = cy + ddy;
                if (x < 0 || x >= G2 || y < 0 || y >= G2) continue;
                const int cell = x * G2 + y;
                const int cnt = min(g_cnt[cell], CAP);
                const float4* __restrict__ p = &g_b[cell * CAP];
                for (int k = sub; k < cnt; k += 8) {
                    const float4 s = p[k];
                    const float dx = s.x - tx, dy = s.y - ty, dz = s.z - tz;
                    b = fminf(b, fmaf(dz, dz, fmaf(dy, dy, dx * dx)));
                }
            }
        } else {
            // Extreme outlier: whole-block brute force, 4-way ILP.
            float b0 = CUDART_INF_F, b1 = CUDART_INF_F;
            float b2 = CUDART_INF_F, b3 = CUDART_INF_F;
            int k = tid;
            for (; k + 768 < N; k += 1024) {
                const float4 s0 = g_all[k];
                const float4 s1 = g_all[k + 256];
                const float4 s2 = g_all[k + 512];
                const float4 s3 = g_all[k + 768];
                float dx, dy, dz;
                dx = s0.x - tx; dy = s0.y - ty; dz = s0.z - tz;
                b0 = fminf(b0, fmaf(dz, dz, fmaf(dy, dy, dx * dx)));
                dx = s1.x - tx; dy = s1.y - ty; dz = s1.z - tz;
                b1 = fminf(b1, fmaf(dz, dz, fmaf(dy, dy, dx * dx)));
                dx = s2.x - tx; dy = s2.y - ty; dz = s2.z - tz;
                b2 = fminf(b2, fmaf(dz, dz, fmaf(dy, dy, dx * dx)));
                dx = s3.x - tx; dy = s3.y - ty; dz = s3.z - tz;
                b3 = fminf(b3, fmaf(dz, dz, fmaf(dy, dy, dx * dx)));
            }
            for (; k < N; k += 256) {
                const float4 s = g_all[k];
                const float dx = s.x - tx, dy = s.y - ty, dz = s.z - tz;
                b0 = fminf(b0, fmaf(dz, dz, fmaf(dy, dy, dx * dx)));
            }
            b = fminf(fminf(b0, b1), fminf(b2, b3));
        }

        shf[tid] = b;
        __syncthreads();
        #pragma unroll
        for (int o = 128; o > 0; o >>= 1) {
            if (tid < o) shf[tid] = fminf(shf[tid], shf[tid + o]);
            __syncthreads();
        }
        if (tid == 0) atomicAdd(&g_acc, fix_of(fminf(shf[0], seed)));
        __syncthreads();
    }

    // ---- last-block finish: write output, reset state for next replay ----
    __syncthreads();
    if (tid == 0) {
        __threadfence();
        sh_last = (atomicAdd(&g_done, 1) == gridDim.x - 1);
    }
    __syncthreads();
    if (sh_last) {
        if (tid == 0) {
            __threadfence();   // acquire: all g_acc contributions visible
            out[0] = (float)(0.5 * ((double)g_acc / FIXSCALE));
            g_acc = 0ull;
            g_flagcnt = 0;
            g_done = 0;
        }
        for (int i = tid; i < NC2; i += blockDim.x)
            g_cnt[i] = 0;
    }
}

extern "C" void kernel_launch(void* const* d_in, const int* in_sizes, int n_in,
                              void* d_out, int out_size) {
    const float* src = (const float*)d_in[0];   // [N,3]
    const float* tar = (const float*)d_in[1];   // [M,3]
    float* out = (float*)d_out;

    const int N = in_sizes[0] / 3;
    const int M = in_sizes[1] / 3;

    rl_build_kernel<<<(N + 255) / 256, 256>>>(src, N);
    rl_query_kernel<<<(M * 32 + 255) / 256, 256>>>(tar, M);
    rl_fixup_kernel<<<FIXUP_BLOCKS, 256>>>(tar, N, out);
}

// round 14
// speedup vs baseline: 1.0877x; 1.0877x over previous
#include <cuda_runtime.h>
#include <math_constants.h>

// ---------------------------------------------------------------------------
// ReverseLossLayer: loss = 0.5 * sum_m  min_n || src[n] - tar[m] ||^2
// Exact 1-NN via 2-D (x,y) bucket grid, 48x48 over [-5,5]^2. 4 graph nodes:
//   build -> query(3x3, prefetched counts) -> fixup(block/target) -> finish
// State contract: g_cnt / g_acc / g_flagcnt are ZERO at entry (CUDA zero-init
// on first call; the finish node re-zeros them for the next replay). Bucket
// slot order is nondeterministic but min over a bucket is order-invariant.
// Reduction uses exact fixed-point u64 atomics (order-invariant).
// ---------------------------------------------------------------------------

#define MAX_M 16384
#define G2 48
#define NC2 (G2 * G2)               // 2304 cells
#define CAP 192                     // lambda_max ~ 113; overflow P ~ 1e-11
#define BASEC (-5.0f)
#define INVH 4.8f                   // G2 / 10
#define FIXSCALE 4294967296.0       // 2^32
#define RMAX 4                      // ring cutoff; beyond -> brute force

__device__ int                g_cnt[NC2];          // zero-init
__device__ float4             g_b[NC2 * CAP];      // ~14 MB bucket scratch
__device__ float4             g_all[MAX_M];        // compact unordered copy
__device__ float              g_min[MAX_M];
__device__ unsigned long long g_acc;               // zero-init
__device__ int                g_flag[MAX_M];
__device__ int                g_flagcnt;           // zero-init

__device__ __forceinline__ int cell_of(float v) {
    int c = (int)floorf((v - BASEC) * INVH);
    return min(max(c, 0), G2 - 1);
}

// Sufficient xy-index radius: any point with d < sqrt(best) lies within
// index distance floor(sqrt(best)*INVH) + 1 (clamping only contracts).
__device__ __forceinline__ int rn_of(float best) {
    if (!(best < CUDART_INF_F)) return 1 << 20;
    return (int)fmaf(sqrtf(best), INVH, 1.001f);
}

__device__ __forceinline__ unsigned long long fix_of(float best) {
    return (unsigned long long)((double)best * FIXSCALE);
}

__global__ void rl_build_kernel(const float* __restrict__ src, int N) {
    const int i = blockIdx.x * blockDim.x + threadIdx.x;
    if (i >= N) return;
    const float x = src[3*i], y = src[3*i+1], z = src[3*i+2];
    g_all[i] = make_float4(x, y, z, 0.0f);          // compact copy for brute
    const int cell = cell_of(x) * G2 + cell_of(y);
    const int slot = atomicAdd(&g_cnt[cell], 1);
    if (slot < CAP) g_b[cell * CAP + slot] = make_float4(x, y, z, 0.0f);
}

// Warp per target: 3x3 xy cells; counts PREFETCHED (9 independent loads ->
// one L2 round-trip), then every lane strides each bucket's float4 points.
__global__ __launch_bounds__(256)
void rl_query_kernel(const float* __restrict__ tar, int M) {
    const int gtid = blockIdx.x * blockDim.x + threadIdx.x;
    const int t = gtid >> 5, lane = gtid & 31;
    if (t >= M) return;

    const float tx = tar[3*t], ty = tar[3*t+1], tz = tar[3*t+2];
    const int cx = cell_of(tx), cy = cell_of(ty);

    int cells[9], cnts[9];
    #pragma unroll
    for (int i = 0; i < 9; i++) {
        const int x = cx + i / 3 - 1;
        const int y = cy + i % 3 - 1;
        const bool ok = (x >= 0 && x < G2 && y >= 0 && y < G2);
        const int cell = ok ? (x * G2 + y) : 0;
        cells[i] = cell;
        cnts[i] = ok ? min(g_cnt[cell], CAP) : 0;
    }

    float best = CUDART_INF_F;
    #pragma unroll
    for (int i = 0; i < 9; i++) {
        const int cnt = cnts[i];
        const float4* __restrict__ p = &g_b[cells[i] * CAP];
        for (int k = lane; k < cnt; k += 32) {
            const float4 s = p[k];
            const float ddx = s.x - tx, ddy = s.y - ty, ddz = s.z - tz;
            best = fminf(best, fmaf(ddz, ddz, fmaf(ddy, ddy, ddx * ddx)));
        }
    }
    #pragma unroll
    for (int o = 16; o > 0; o >>= 1)
        best = fminf(best, __shfl_xor_sync(0xFFFFFFFFu, best, o));

    if (lane == 0) {
        g_min[t] = best;
        if (rn_of(best) <= 1) atomicAdd(&g_acc, fix_of(best));
        else                  g_flag[atomicAdd(&g_flagcnt, 1)] = t;
    }
}

// BLOCK per flagged target. Ring path: 8 threads per cell (coalesced bucket
// reads), 32 cells per round. Brute path (Rn>RMAX or empty seed): 256-thread
// ILP-unrolled scan of the compact point array.
__global__ __launch_bounds__(256)
void rl_fixup_kernel(const float* __restrict__ tar, int N) {
    __shared__ float shf[256];
    const int tid = threadIdx.x;
    const int nf = g_flagcnt;

    for (int fi = blockIdx.x; fi < nf; fi += gridDim.x) {
        const int t = g_flag[fi];
        const float tx = tar[3*t], ty = tar[3*t+1], tz = tar[3*t+2];

        const float seed = g_min[t];
        const int Rn = rn_of(seed);
        float b = CUDART_INF_F;

        if (Rn <= RMAX) {
            const int cx = cell_of(tx), cy = cell_of(ty);
            const int grp = tid >> 3, sub = tid & 7;
            const int W2 = 2 * Rn + 1, ncells = W2 * W2;
            for (int c = grp; c < ncells; c += 32) {
                const int ddx = c / W2 - Rn;
                const int ddy = c % W2 - Rn;
                if (abs(ddx) <= 1 && abs(ddy) <= 1) continue;   // 3x3 done
                const int x = cx + ddx, y = cy + ddy;
                if (x < 0 || x >= G2 || y < 0 || y >= G2) continue;
                const int cell = x * G2 + y;
                const int cnt = min(g_cnt[cell], CAP);
                const float4* __restrict__ p = &g_b[cell * CAP];
                for (int k = sub; k < cnt; k += 8) {
                    const float4 s = p[k];
                    const float dx = s.x - tx, dy = s.y - ty, dz = s.z - tz;
                    b = fminf(b, fmaf(dz, dz, fmaf(dy, dy, dx * dx)));
                }
            }
        } else {
            float b0 = CUDART_INF_F, b1 = CUDART_INF_F;
            float b2 = CUDART_INF_F, b3 = CUDART_INF_F;
            int k = tid;
            for (; k + 768 < N; k += 1024) {
                const float4 s0 = g_all[k];
                const float4 s1 = g_all[k + 256];
                const float4 s2 = g_all[k + 512];
                const float4 s3 = g_all[k + 768];
                float dx, dy, dz;
                dx = s0.x - tx; dy = s0.y - ty; dz = s0.z - tz;
                b0 = fminf(b0, fmaf(dz, dz, fmaf(dy, dy, dx * dx)));
                dx = s1.x - tx; dy = s1.y - ty; dz = s1.z - tz;
                b1 = fminf(b1, fmaf(dz, dz, fmaf(dy, dy, dx * dx)));
                dx = s2.x - tx; dy = s2.y - ty; dz = s2.z - tz;
                b2 = fminf(b2, fmaf(dz, dz, fmaf(dy, dy, dx * dx)));
                dx = s3.x - tx; dy = s3.y - ty; dz = s3.z - tz;
                b3 = fminf(b3, fmaf(dz, dz, fmaf(dy, dy, dx * dx)));
            }
            for (; k < N; k += 256) {
                const float4 s = g_all[k];
                const float dx = s.x - tx, dy = s.y - ty, dz = s.z - tz;
                b0 = fminf(b0, fmaf(dz, dz, fmaf(dy, dy, dx * dx)));
            }
            b = fminf(fminf(b0, b1), fminf(b2, b3));
        }

        shf[tid] = b;
        __syncthreads();
        #pragma unroll
        for (int o = 128; o > 0; o >>= 1) {
            if (tid < o) shf[tid] = fminf(shf[tid], shf[tid + o]);
            __syncthreads();
        }
        if (tid == 0) atomicAdd(&g_acc, fix_of(fminf(shf[0], seed)));
        __syncthreads();
    }
}

// Writes the result AND resets all mutated persistent state so that the next
// graph replay starts from the same (zeroed) state as the first call.
__global__ void rl_finish_kernel(float* __restrict__ out) {
    const int tid = threadIdx.x;
    if (tid == 0) {
        out[0] = (float)(0.5 * ((double)g_acc / FIXSCALE));
        g_acc = 0ull;
        g_flagcnt = 0;
    }
    for (int i = tid; i < NC2; i += blockDim.x)
        g_cnt[i] = 0;
}

extern "C" void kernel_launch(void* const* d_in, const int* in_sizes, int n_in,
                              void* d_out, int out_size) {
    const float* src = (const float*)d_in[0];   // [N,3]
    const float* tar = (const float*)d_in[1];   // [M,3]
    float* out = (float*)d_out;

    const int N = in_sizes[0] / 3;
    const int M = in_sizes[1] / 3;

    rl_build_kernel<<<(N + 255) / 256, 256>>>(src, N);
    rl_query_kernel<<<(M * 32 + 255) / 256, 256>>>(tar, M);
    rl_fixup_kernel<<<296, 256>>>(tar, N);
    rl_finish_kernel<<<1, 256>>>(out);
}